// round 2
// baseline (speedup 1.0000x reference)
#include <cuda_runtime.h>
#include <math.h>

// ---------------- problem dims ----------------
#define KB   16384          // num codebooks
#define NN   8192           // B*64 tokens after conv
#define M1   32768          // B*S rows for GEMM1
#define DD   128            // embedding dim
#define DIMI 512            // input feature dim

// ---------------- scratch (device globals; no mallocs allowed) ----------------
__device__ float g_h[M1 * DD];          // encode diff after GEMM1   [32768,128]
__device__ float g_x[NN * DD];          // conv output (VQ input)    [8192,128]
__device__ float g_q[NN * DD];          // quantized                 [8192,128]
__device__ float g_wt[9 * DD * DD];     // conv weights [kk][din][dout]
__device__ float g_cnorm[KB];           // 0.5*|c|^2
__device__ float g_counts[KB];
__device__ int   g_idx[NN];

// ============================================================
// Prep: transpose conv weights  conv_w[dout][din][kh][kw] -> g_wt[kk][din][dout]
// ============================================================
__global__ void k_prep(const float* __restrict__ cw) {
    int i = blockIdx.x * 256 + threadIdx.x;         // 9*128*128 = 147456
    if (i < 9 * DD * DD) {
        int dout = i & 127;
        int din  = (i >> 7) & 127;
        int kk   = i >> 14;
        g_wt[i] = cw[(dout * DD + din) * 9 + kk];
    }
}

// ============================================================
// cnorm (0.5*|c|^2) + zero counts
// ============================================================
__global__ void k_cnorm(const float* __restrict__ cb) {
    int k = blockIdx.x * 256 + threadIdx.x;
    if (k < KB) {
        const float4* p = (const float4*)(cb + (size_t)k * DD);
        float s = 0.f;
        #pragma unroll
        for (int i = 0; i < 32; i++) {
            float4 v = p[i];
            s += v.x * v.x + v.y * v.y + v.z * v.z + v.w * v.w;
        }
        g_cnorm[k]  = 0.5f * s;
        g_counts[k] = 0.f;
    }
}

// ============================================================
// GEMM1: g_h[m,n] = sum_k (last[m,k]-first[m,k]) * W_in[k,n]
// M=32768, K=512, N=128.  128x128 block tile, 8x8 micro.
// ============================================================
__global__ void __launch_bounds__(256) k_gemm1(const float* __restrict__ A1,
                                               const float* __restrict__ A0,
                                               const float* __restrict__ W) {
    __shared__ float As[16][132];   // [k][m]
    __shared__ float Bs[16][128];   // [k][n]
    int tid  = threadIdx.x;
    int m0   = blockIdx.x * 128;
    int row0 = (tid >> 4) << 3;
    int col0 = (tid & 15) << 3;
    int ml   = tid >> 2;            // 0..63
    int kq   = (tid & 3) << 2;      // 0,4,8,12

    float acc[8][8];
    #pragma unroll
    for (int i = 0; i < 8; i++)
        #pragma unroll
        for (int j = 0; j < 8; j++) acc[i][j] = 0.f;

    for (int k0 = 0; k0 < DIMI; k0 += 16) {
        #pragma unroll
        for (int pass = 0; pass < 2; pass++) {
            int m = ml + pass * 64;
            const float4 v1 = *(const float4*)(A1 + (size_t)(m0 + m) * DIMI + k0 + kq);
            const float4 v0 = *(const float4*)(A0 + (size_t)(m0 + m) * DIMI + k0 + kq);
            As[kq + 0][m] = v1.x - v0.x;
            As[kq + 1][m] = v1.y - v0.y;
            As[kq + 2][m] = v1.z - v0.z;
            As[kq + 3][m] = v1.w - v0.w;
        }
        {
            int n4 = (tid & 31) << 2;
            int kr = tid >> 5;
            #pragma unroll
            for (int pass = 0; pass < 2; pass++)
                *(float4*)&Bs[kr + pass * 8][n4] =
                    *(const float4*)(W + (size_t)(k0 + kr + pass * 8) * DD + n4);
        }
        __syncthreads();
        #pragma unroll
        for (int kk = 0; kk < 16; kk++) {
            float a[8], b[8];
            *(float4*)(a)     = *(const float4*)&As[kk][row0];
            *(float4*)(a + 4) = *(const float4*)&As[kk][row0 + 4];
            *(float4*)(b)     = *(const float4*)&Bs[kk][col0];
            *(float4*)(b + 4) = *(const float4*)&Bs[kk][col0 + 4];
            #pragma unroll
            for (int i = 0; i < 8; i++)
                #pragma unroll
                for (int j = 0; j < 8; j++) acc[i][j] += a[i] * b[j];
        }
        __syncthreads();
    }
    #pragma unroll
    for (int i = 0; i < 8; i++) {
        float4 o0 = make_float4(acc[i][0], acc[i][1], acc[i][2], acc[i][3]);
        float4 o1 = make_float4(acc[i][4], acc[i][5], acc[i][6], acc[i][7]);
        *(float4*)&g_h[(size_t)(m0 + row0 + i) * DD + col0]     = o0;
        *(float4*)&g_h[(size_t)(m0 + row0 + i) * DD + col0 + 4] = o1;
    }
}

// ============================================================
// Conv 3x3 stride2 pad1 as 9 accumulated GEMMs.
// g_x[p,dout] = sum_kk sum_din H[b,din,ih,iw]*W[dout,din,kh,kw]
// where p=b*64+oh*8+ow, H row = g_h[(b*256+ih*16+iw)*128 + din].
// Block: 64p x 128dout. micro 8x4.
// ============================================================
__global__ void __launch_bounds__(256) k_conv() {
    __shared__ float As[16][68];    // [din][p]
    __shared__ float Ws[16][128];   // [din][dout]
    int tid  = threadIdx.x;
    int p0   = blockIdx.x * 64;
    int row0 = (tid >> 5) << 3;     // p
    int col0 = (tid & 31) << 2;     // dout
    int pl   = tid >> 2;            // 0..63
    int d4   = (tid & 3) << 2;      // 0,4,8,12

    int p  = p0 + pl;
    int b  = p >> 6;
    int jj = p & 63;
    int oh = jj >> 3, ow = jj & 7;

    float acc[8][4];
    #pragma unroll
    for (int i = 0; i < 8; i++)
        #pragma unroll
        for (int j = 0; j < 4; j++) acc[i][j] = 0.f;

    #pragma unroll
    for (int kk = 0; kk < 9; kk++) {
        int kh = kk / 3, kw = kk % 3;
        int ih = 2 * oh - 1 + kh;
        int iw = 2 * ow - 1 + kw;
        bool valid = ((unsigned)ih < 16u) && ((unsigned)iw < 16u);
        const float* hrow = g_h + (size_t)(b * 256 + ih * 16 + iw) * DD;

        for (int dt = 0; dt < 8; dt++) {
            float4 v = make_float4(0.f, 0.f, 0.f, 0.f);
            if (valid) v = *(const float4*)(hrow + dt * 16 + d4);
            As[d4 + 0][pl] = v.x;
            As[d4 + 1][pl] = v.y;
            As[d4 + 2][pl] = v.z;
            As[d4 + 3][pl] = v.w;
            #pragma unroll
            for (int it = 0; it < 2; it++) {
                int vv = it * 256 + tid;
                int dl = vv >> 5;
                int n4 = (vv & 31) << 2;
                *(float4*)&Ws[dl][n4] =
                    *(const float4*)&g_wt[kk * (DD * DD) + (dt * 16 + dl) * DD + n4];
            }
            __syncthreads();
            #pragma unroll
            for (int dl = 0; dl < 16; dl++) {
                float a[8], w[4];
                *(float4*)(a)     = *(const float4*)&As[dl][row0];
                *(float4*)(a + 4) = *(const float4*)&As[dl][row0 + 4];
                *(float4*)(w)     = *(const float4*)&Ws[dl][col0];
                #pragma unroll
                for (int i = 0; i < 8; i++)
                    #pragma unroll
                    for (int j = 0; j < 4; j++) acc[i][j] += a[i] * w[j];
            }
            __syncthreads();
        }
    }
    #pragma unroll
    for (int i = 0; i < 8; i++) {
        float4 o = make_float4(acc[i][0], acc[i][1], acc[i][2], acc[i][3]);
        *(float4*)&g_x[(size_t)(p0 + row0 + i) * DD + col0] = o;
    }
}

// ============================================================
// VQ argmin:  score[n,k] = 0.5*|c_k|^2 - x_n . c_k  (same ordering as dists)
// Block: 64 n rows, loop over all K in tiles of 256.
// threads 256 = 8 warps (tn) x 32 lanes (tk); micro 8n x 8k (k = tk + 32j).
// ============================================================
#define VQ_KT 256
#define CS_STRIDE 133
#define VQ_SMEM ((128 * 64 + VQ_KT * CS_STRIDE + VQ_KT) * 4)

__global__ void __launch_bounds__(256) k_vq(const float* __restrict__ cb) {
    extern __shared__ float sm[];
    float* xs  = sm;                         // [128][64]   (d-major)
    float* Cs  = sm + 128 * 64;              // [256][133]  (k-major, pad 133)
    float* cns = Cs + VQ_KT * CS_STRIDE;     // [256]

    int tid = threadIdx.x;
    int tn  = tid >> 5;   // warp
    int tk  = tid & 31;   // lane
    int n0  = blockIdx.x * 64;

    // load x tile (transposed to [d][n])
    #pragma unroll
    for (int it = 0; it < 8; it++) {
        int v  = it * 256 + tid;
        int nl = v >> 5;
        int dq = (v & 31) << 2;
        float4 val = *(const float4*)&g_x[(size_t)(n0 + nl) * DD + dq];
        xs[(dq + 0) * 64 + nl] = val.x;
        xs[(dq + 1) * 64 + nl] = val.y;
        xs[(dq + 2) * 64 + nl] = val.z;
        xs[(dq + 3) * 64 + nl] = val.w;
    }

    float minv[8];
    int   mini[8];
    #pragma unroll
    for (int i = 0; i < 8; i++) { minv[i] = 1e30f; mini[i] = 0; }

    const float* xb = xs + tn * 8;
    const float* cb0 = Cs + tk * CS_STRIDE;

    for (int kt = 0; kt < KB / VQ_KT; kt++) {
        int kbase = kt * VQ_KT;
        #pragma unroll 8
        for (int it = 0; it < 32; it++) {
            int v  = it * 256 + tid;
            int kl = v >> 5;
            int dq = (v & 31) << 2;
            float4 val = *(const float4*)&cb[(size_t)(kbase + kl) * DD + dq];
            float* dst = &Cs[kl * CS_STRIDE + dq];
            dst[0] = val.x; dst[1] = val.y; dst[2] = val.z; dst[3] = val.w;
        }
        cns[tid] = g_cnorm[kbase + tid];
        if (tid + 256 < VQ_KT) {}   // VQ_KT==256: one per thread
        __syncthreads();

        float acc[8][8];
        #pragma unroll
        for (int i = 0; i < 8; i++)
            #pragma unroll
            for (int j = 0; j < 8; j++) acc[i][j] = 0.f;

        #pragma unroll 4
        for (int d = 0; d < DD; d++) {
            float a[8], c[8];
            *(float4*)(a)     = *(const float4*)(xb + d * 64);
            *(float4*)(a + 4) = *(const float4*)(xb + d * 64 + 4);
            #pragma unroll
            for (int j = 0; j < 8; j++) c[j] = cb0[j * (32 * CS_STRIDE) + d];
            #pragma unroll
            for (int i = 0; i < 8; i++)
                #pragma unroll
                for (int j = 0; j < 8; j++) acc[i][j] += a[i] * c[j];
        }

        #pragma unroll
        for (int j = 0; j < 8; j++) {
            int   kg = kbase + tk + 32 * j;
            float cn = cns[tk + 32 * j];
            #pragma unroll
            for (int i = 0; i < 8; i++) {
                float s = cn - acc[i][j];
                if (s < minv[i]) { minv[i] = s; mini[i] = kg; }
            }
        }
        __syncthreads();
    }

    // warp-level argmin reduction over lanes (tie -> lowest index)
    #pragma unroll
    for (int i = 0; i < 8; i++) {
        float v  = minv[i];
        int   id = mini[i];
        #pragma unroll
        for (int off = 16; off; off >>= 1) {
            float ov = __shfl_down_sync(0xffffffffu, v, off);
            int   oi = __shfl_down_sync(0xffffffffu, id, off);
            if (ov < v || (ov == v && oi < id)) { v = ov; id = oi; }
        }
        if (tk == 0) g_idx[n0 + tn * 8 + i] = id;
    }
}

// ============================================================
// Post: quantized = x + (||x-c||/||rv|| + eps)*rv ; counts atomic
// one warp per token
// ============================================================
__global__ void k_post(const float* __restrict__ cb, const float* __restrict__ rv) {
    int gw   = (blockIdx.x * blockDim.x + threadIdx.x) >> 5;
    int lane = threadIdx.x & 31;
    if (gw >= NN) return;
    int idx = g_idx[gw];
    const float* xp = g_x + (size_t)gw * DD;
    const float* cp = cb + (size_t)idx * DD;
    const float* rp = rv + (size_t)gw * DD;
    float xr[4], rr[4];
    float sr = 0.f, sn = 0.f;
    #pragma unroll
    for (int t = 0; t < 4; t++) {
        int d = lane + t * 32;
        float xv = xp[d], cv = cp[d], rvv = rp[d];
        xr[t] = xv; rr[t] = rvv;
        float df = xv - cv;
        sr += df * df;
        sn += rvv * rvv;
    }
    #pragma unroll
    for (int o = 16; o; o >>= 1) {
        sr += __shfl_xor_sync(0xffffffffu, sr, o);
        sn += __shfl_xor_sync(0xffffffffu, sn, o);
    }
    float ratio = sqrtf(sr) / sqrtf(sn) + 1e-12f;
    float* qp = g_q + (size_t)gw * DD;
    #pragma unroll
    for (int t = 0; t < 4; t++) qp[lane + t * 32] = xr[t] + ratio * rr[t];
    if (lane == 0) atomicAdd(&g_counts[idx], 1.0f);
}

// ============================================================
// Final scalars: perplexity, new_used, min_indices (as float)
// out layout: [0,4194304) decode ; [4194304] perp ; [4194305,+16384) used ; then 8192 idx
// ============================================================
__global__ void k_final(const int* __restrict__ used, float* __restrict__ out) {
    __shared__ float red[256];
    int tid = threadIdx.x;
    float s = 0.f;
    for (int k = tid; k < KB; k += 256) {
        float p = g_counts[k] * (1.0f / 8192.0f);
        s += p * logf(p + 1e-12f);
    }
    red[tid] = s;
    __syncthreads();
    for (int o = 128; o; o >>= 1) {
        if (tid < o) red[tid] += red[tid + o];
        __syncthreads();
    }
    if (tid == 0) out[4194304] = expf(-red[0]);
    for (int k = tid; k < KB; k += 256)
        out[4194305 + k] = (float)(used[k] + (int)g_counts[k]);
    for (int n = tid; n < NN; n += 256)
        out[4194305 + KB + n] = (float)g_idx[n];
}

// ============================================================
// Decode GEMM: out[p, n] = sum_d A[p,d]*W_out[d,n] + b_out[n]
// A[p,d] = g_q_flat[b*8192 + d*64 + j], p=b*64+j  (raw reinterpret shuffle)
// M=8192, K=128, N=512.
// ============================================================
__global__ void __launch_bounds__(256) k_dec(const float* __restrict__ Wout,
                                             const float* __restrict__ bout,
                                             float* __restrict__ out) {
    __shared__ float As[16][132];
    __shared__ float Bs[16][128];
    int tid  = threadIdx.x;
    int m0   = (blockIdx.x >> 2) * 128;
    int n0   = (blockIdx.x & 3) * 128;
    int row0 = (tid >> 4) << 3;
    int col0 = (tid & 15) << 3;

    float acc[8][8];
    #pragma unroll
    for (int i = 0; i < 8; i++)
        #pragma unroll
        for (int j = 0; j < 8; j++) acc[i][j] = 0.f;

    for (int k0 = 0; k0 < DD; k0 += 16) {
        #pragma unroll
        for (int it = 0; it < 2; it++) {
            int v  = it * 256 + tid;
            int kl = v >> 5;
            int r  = v & 31;
            int bl = r >> 4;
            int j4 = (r & 15) << 2;
            int bg = (m0 >> 6) + bl;
            float4 val = *(const float4*)&g_q[(size_t)bg * 8192 + (k0 + kl) * 64 + j4];
            *(float4*)&As[kl][bl * 64 + j4] = val;
        }
        {
            int n4 = (tid & 31) << 2;
            int kr = tid >> 5;
            #pragma unroll
            for (int pass = 0; pass < 2; pass++)
                *(float4*)&Bs[kr + pass * 8][n4] =
                    *(const float4*)(Wout + (size_t)(k0 + kr + pass * 8) * DIMI + n0 + n4);
        }
        __syncthreads();
        #pragma unroll
        for (int kk = 0; kk < 16; kk++) {
            float a[8], b[8];
            *(float4*)(a)     = *(const float4*)&As[kk][row0];
            *(float4*)(a + 4) = *(const float4*)&As[kk][row0 + 4];
            *(float4*)(b)     = *(const float4*)&Bs[kk][col0];
            *(float4*)(b + 4) = *(const float4*)&Bs[kk][col0 + 4];
            #pragma unroll
            for (int i = 0; i < 8; i++)
                #pragma unroll
                for (int j = 0; j < 8; j++) acc[i][j] += a[i] * b[j];
        }
        __syncthreads();
    }
    #pragma unroll
    for (int i = 0; i < 8; i++) {
        #pragma unroll
        for (int j = 0; j < 8; j++) {
            out[(size_t)(m0 + row0 + i) * DIMI + n0 + col0 + j] =
                acc[i][j] + bout[n0 + col0 + j];
        }
    }
}

// ============================================================
extern "C" void kernel_launch(void* const* d_in, const int* in_sizes, int n_in,
                              void* d_out, int out_size) {
    (void)in_sizes; (void)n_in; (void)out_size;
    const float* in_f   = (const float*)d_in[0];
    const float* in_l   = (const float*)d_in[1];
    const float* rv     = (const float*)d_in[2];
    const float* cb     = (const float*)d_in[3];
    const float* W_in   = (const float*)d_in[4];
    const float* conv_w = (const float*)d_in[6];
    const float* W_out  = (const float*)d_in[8];
    const float* b_out  = (const float*)d_in[9];
    const int*   used   = (const int*)d_in[10];
    float* out = (float*)d_out;

    cudaFuncSetAttribute(k_vq, cudaFuncAttributeMaxDynamicSharedMemorySize, VQ_SMEM);

    k_prep <<<576, 256>>>(conv_w);
    k_cnorm<<<64, 256>>>(cb);
    k_gemm1<<<256, 256>>>(in_l, in_f, W_in);
    k_conv <<<128, 256>>>();
    k_vq   <<<128, 256, VQ_SMEM>>>(cb);
    k_post <<<1024, 256>>>(cb, rv);
    k_final<<<1, 256>>>(used, out);
    k_dec  <<<256, 256>>>(W_out, b_out, out);
}

// round 4
// speedup vs baseline: 2.0993x; 2.0993x over previous
#include <cuda_runtime.h>
#include <cuda_bf16.h>
#include <math.h>
#include <stdint.h>

// ---------------- problem dims ----------------
#define KB   16384
#define NN   8192
#define M1   32768
#define DD   128
#define DIMI 512
#define CAP  64

// ---------------- scratch ----------------
__device__ float g_h[M1 * DD];
__device__ float g_x[NN * DD];
__device__ float g_q[NN * DD];
__device__ float g_wt[9 * DD * DD];
__device__ float g_cnorm[KB];
__device__ float g_counts[KB];
__device__ int   g_idx[NN];
__device__ __nv_bfloat16 g_xs[NN * DD];           // x hi (bf16)
__device__ __nv_bfloat16 g_cs[(size_t)KB * DD];   // codebook hi (bf16)
__device__ float g_xnorm[NN];
__device__ int   g_cmax_bits;
__device__ int   g_ccount[NN];
__device__ int   g_cand[NN * CAP];

// ---------------- helpers ----------------
__device__ __forceinline__ uint32_t smem_u32(const void* p) {
    uint32_t a;
    asm("{ .reg .u64 t; cvta.to.shared.u64 t, %1; cvt.u32.u64 %0, t; }" : "=r"(a) : "l"(p));
    return a;
}
__device__ __forceinline__ void cp16(uint32_t dst, const void* src) {
    asm volatile("cp.async.cg.shared.global [%0], [%1], 16;\n" :: "r"(dst), "l"(src));
}
#define CP_COMMIT()  asm volatile("cp.async.commit_group;\n" ::: "memory")
#define CP_WAIT0()   asm volatile("cp.async.wait_group 0;\n" ::: "memory")
#define CP_WAIT1()   asm volatile("cp.async.wait_group 1;\n" ::: "memory")

__device__ __forceinline__ void ldsm4(uint32_t& r0, uint32_t& r1, uint32_t& r2, uint32_t& r3,
                                      uint32_t a) {
    asm volatile("ldmatrix.sync.aligned.m8n8.x4.shared.b16 {%0,%1,%2,%3}, [%4];"
                 : "=r"(r0), "=r"(r1), "=r"(r2), "=r"(r3) : "r"(a));
}
__device__ __forceinline__ void mma16816(float* d, const uint32_t* a, uint32_t b0, uint32_t b1) {
    asm volatile("mma.sync.aligned.m16n8k16.row.col.f32.bf16.bf16.f32 "
                 "{%0,%1,%2,%3}, {%4,%5,%6,%7}, {%8,%9}, {%0,%1,%2,%3};"
                 : "+f"(d[0]), "+f"(d[1]), "+f"(d[2]), "+f"(d[3])
                 : "r"(a[0]), "r"(a[1]), "r"(a[2]), "r"(a[3]), "r"(b0), "r"(b1));
}

// ============================================================
// Prep: conv weight transpose + cmax init
// ============================================================
__global__ void k_prep(const float* __restrict__ cw) {
    int i = blockIdx.x * 256 + threadIdx.x;
    if (i == 0) g_cmax_bits = 0;
    if (i < 9 * DD * DD) {
        int dout = i & 127;
        int din  = (i >> 7) & 127;
        int kk   = i >> 14;
        g_wt[i] = cw[(dout * DD + din) * 9 + kk];
    }
}

// ============================================================
// cnorm (0.5*|c|^2), cmax, zero counters, codebook hi split
// ============================================================
__global__ void k_cnorm(const float* __restrict__ cb) {
    int k = blockIdx.x * 256 + threadIdx.x;
    if (k < KB) {
        const float4* p = (const float4*)(cb + (size_t)k * DD);
        float s = 0.f;
        #pragma unroll
        for (int i = 0; i < 32; i++) {
            float4 v = p[i];
            s += v.x * v.x + v.y * v.y + v.z * v.z + v.w * v.w;
        }
        g_cnorm[k]  = 0.5f * s;
        g_counts[k] = 0.f;
        if (k < NN) g_ccount[k] = 0;
        atomicMax(&g_cmax_bits, __float_as_int(sqrtf(s)));
    }
}

__global__ void k_splitc(const float* __restrict__ cb) {
    int i = blockIdx.x * 256 + threadIdx.x;   // KB*128
    if (i < KB * DD) g_cs[i] = __float2bfloat16(cb[i]);
}

// ============================================================
// x hi split + |x| (one warp per token)
// ============================================================
__global__ void k_splitx() {
    int gw   = blockIdx.x * 8 + (threadIdx.x >> 5);
    int lane = threadIdx.x & 31;
    const float* xp = g_x + (size_t)gw * DD;
    float ss = 0.f;
    #pragma unroll
    for (int t = 0; t < 4; t++) {
        float v = xp[lane + t * 32];
        g_xs[(size_t)gw * DD + lane + t * 32] = __float2bfloat16(v);
        ss += v * v;
    }
    #pragma unroll
    for (int o = 16; o; o >>= 1) ss += __shfl_xor_sync(0xffffffffu, ss, o);
    if (lane == 0) g_xnorm[gw] = sqrtf(ss);
}

// ============================================================
// GEMM1 (unchanged, passing)
// ============================================================
__global__ void __launch_bounds__(256) k_gemm1(const float* __restrict__ A1,
                                               const float* __restrict__ A0,
                                               const float* __restrict__ W) {
    __shared__ float As[16][132];
    __shared__ float Bs[16][128];
    int tid  = threadIdx.x;
    int m0   = blockIdx.x * 128;
    int row0 = (tid >> 4) << 3;
    int col0 = (tid & 15) << 3;
    int ml   = tid >> 2;
    int kq   = (tid & 3) << 2;

    float acc[8][8];
    #pragma unroll
    for (int i = 0; i < 8; i++)
        #pragma unroll
        for (int j = 0; j < 8; j++) acc[i][j] = 0.f;

    for (int k0 = 0; k0 < DIMI; k0 += 16) {
        #pragma unroll
        for (int pass = 0; pass < 2; pass++) {
            int m = ml + pass * 64;
            const float4 v1 = *(const float4*)(A1 + (size_t)(m0 + m) * DIMI + k0 + kq);
            const float4 v0 = *(const float4*)(A0 + (size_t)(m0 + m) * DIMI + k0 + kq);
            As[kq + 0][m] = v1.x - v0.x;
            As[kq + 1][m] = v1.y - v0.y;
            As[kq + 2][m] = v1.z - v0.z;
            As[kq + 3][m] = v1.w - v0.w;
        }
        {
            int n4 = (tid & 31) << 2;
            int kr = tid >> 5;
            #pragma unroll
            for (int pass = 0; pass < 2; pass++)
                *(float4*)&Bs[kr + pass * 8][n4] =
                    *(const float4*)(W + (size_t)(k0 + kr + pass * 8) * DD + n4);
        }
        __syncthreads();
        #pragma unroll
        for (int kk = 0; kk < 16; kk++) {
            float a[8], b[8];
            *(float4*)(a)     = *(const float4*)&As[kk][row0];
            *(float4*)(a + 4) = *(const float4*)&As[kk][row0 + 4];
            *(float4*)(b)     = *(const float4*)&Bs[kk][col0];
            *(float4*)(b + 4) = *(const float4*)&Bs[kk][col0 + 4];
            #pragma unroll
            for (int i = 0; i < 8; i++)
                #pragma unroll
                for (int j = 0; j < 8; j++) acc[i][j] += a[i] * b[j];
        }
        __syncthreads();
    }
    #pragma unroll
    for (int i = 0; i < 8; i++) {
        float4 o0 = make_float4(acc[i][0], acc[i][1], acc[i][2], acc[i][3]);
        float4 o1 = make_float4(acc[i][4], acc[i][5], acc[i][6], acc[i][7]);
        *(float4*)&g_h[(size_t)(m0 + row0 + i) * DD + col0]     = o0;
        *(float4*)&g_h[(size_t)(m0 + row0 + i) * DD + col0 + 4] = o1;
    }
}

// ============================================================
// Conv (unchanged, passing)
// ============================================================
__global__ void __launch_bounds__(256) k_conv() {
    __shared__ float As[16][68];
    __shared__ float Ws[16][128];
    int tid  = threadIdx.x;
    int p0   = blockIdx.x * 64;
    int row0 = (tid >> 5) << 3;
    int col0 = (tid & 31) << 2;
    int pl   = tid >> 2;
    int d4   = (tid & 3) << 2;

    int p  = p0 + pl;
    int b  = p >> 6;
    int jj = p & 63;
    int oh = jj >> 3, ow = jj & 7;

    float acc[8][4];
    #pragma unroll
    for (int i = 0; i < 8; i++)
        #pragma unroll
        for (int j = 0; j < 4; j++) acc[i][j] = 0.f;

    #pragma unroll
    for (int kk = 0; kk < 9; kk++) {
        int kh = kk / 3, kw = kk % 3;
        int ih = 2 * oh - 1 + kh;
        int iw = 2 * ow - 1 + kw;
        bool valid = ((unsigned)ih < 16u) && ((unsigned)iw < 16u);
        const float* hrow = g_h + (size_t)(b * 256 + ih * 16 + iw) * DD;

        for (int dt = 0; dt < 8; dt++) {
            float4 v = make_float4(0.f, 0.f, 0.f, 0.f);
            if (valid) v = *(const float4*)(hrow + dt * 16 + d4);
            As[d4 + 0][pl] = v.x;
            As[d4 + 1][pl] = v.y;
            As[d4 + 2][pl] = v.z;
            As[d4 + 3][pl] = v.w;
            #pragma unroll
            for (int it = 0; it < 2; it++) {
                int vv = it * 256 + tid;
                int dl = vv >> 5;
                int n4 = (vv & 31) << 2;
                *(float4*)&Ws[dl][n4] =
                    *(const float4*)&g_wt[kk * (DD * DD) + (dt * 16 + dl) * DD + n4];
            }
            __syncthreads();
            #pragma unroll
            for (int dl = 0; dl < 16; dl++) {
                float a[8], w[4];
                *(float4*)(a)     = *(const float4*)&As[dl][row0];
                *(float4*)(a + 4) = *(const float4*)&As[dl][row0 + 4];
                *(float4*)(w)     = *(const float4*)&Ws[dl][col0];
                #pragma unroll
                for (int i = 0; i < 8; i++)
                    #pragma unroll
                    for (int j = 0; j < 4; j++) acc[i][j] += a[i] * w[j];
            }
            __syncthreads();
        }
    }
    #pragma unroll
    for (int i = 0; i < 8; i++) {
        float4 o = make_float4(acc[i][0], acc[i][1], acc[i][2], acc[i][3]);
        *(float4*)&g_x[(size_t)(p0 + row0 + i) * DD + col0] = o;
    }
}

// ============================================================
// VQ approximate pass via mma.sync bf16 (hi only) + margin collect.
// grid = 128 CTAs: 32 token-tiles (256 tokens) x 4 code-splits (4096 codes).
// Block tile per iter: 256 tokens x 128 codes. 8 warps = 4(M) x 2(N).
// SMEM rows padded to 272B -> conflict-free ldmatrix.
// ============================================================
#define LDB      272
#define A_OFF    0                     // 256*272 = 69632
#define B_OFF    69632                 // 2 * 128*272 = 69632
#define CNS_OFF  139264                // 2*128*4 = 1024
#define EB2_OFF  140288                // 256*4
#define RMIN_OFF 141312                // 2*256*4
#define RM_OFF   143360                // 256*4
#define VQ_SMEM  144384
#define NIT 32

__device__ __forceinline__ void vq_loadB(uint32_t su, int buf, int kglob, int tid) {
    #pragma unroll
    for (int t = 0; t < 8; t++) {
        int j   = t * 256 + tid;       // 0..2047
        int row = j >> 4;
        int c   = j & 15;
        cp16(su + B_OFF + buf * 34816 + row * LDB + c * 16,
             (const char*)g_cs + ((size_t)(kglob + row) * DD + c * 8) * 2);
    }
}

__global__ void __launch_bounds__(256, 1) k_vqtc() {
    extern __shared__ char smc[];
    uint32_t su = smem_u32(smc);
    int tid  = threadIdx.x;
    int wid  = tid >> 5;
    int lane = tid & 31;
    int wm   = wid & 3;       // M warp (64 tokens)
    int wn   = wid >> 2;      // N warp (64 codes)
    int tt   = blockIdx.x >> 2;
    int sp   = blockIdx.x & 3;
    int kb0  = sp * 4096;

    float* cns  = (float*)(smc + CNS_OFF);
    float* eb2  = (float*)(smc + EB2_OFF);
    float* rmin = (float*)(smc + RMIN_OFF);
    float* rm   = (float*)(smc + RM_OFF);

    // ---- prologue loads ----
    #pragma unroll
    for (int t = 0; t < 16; t++) {     // A: 256 rows x 256B
        int i   = t * 256 + tid;
        int row = i >> 4;
        int c   = i & 15;
        cp16(su + A_OFF + row * LDB + c * 16,
             (const char*)g_xs + ((size_t)(tt * 256 + row) * DD + c * 8) * 2);
    }
    vq_loadB(su, 0, kb0, tid);
    CP_COMMIT();
    vq_loadB(su, 1, kb0 + 128, tid);
    CP_COMMIT();

    if (tid < 128) {
        cns[tid]       = g_cnorm[kb0 + tid];
        cns[128 + tid] = g_cnorm[kb0 + 128 + tid];
    }
    {
        float cmax = __int_as_float(g_cmax_bits);
        float xn = g_xnorm[tt * 256 + tid];
        eb2[tid] = 2.f * (0.0041f * xn * cmax) + 0.1f;
        rm[tid] = 1e30f;
    }
    CP_WAIT1();
    __syncthreads();

    // per-thread ldmatrix bases
    uint32_t aBase = su + A_OFF + (wm * 64 + (lane & 15)) * LDB + (lane >> 4) * 16;
    uint32_t bBase = su + B_OFF + (wn * 64 + (lane & 15)) * LDB + (lane >> 4) * 16;

    for (int it = 0; it < NIT; it++) {
        int buf = it & 1;
        float acc[4][8][4];
        #pragma unroll
        for (int mt = 0; mt < 4; mt++)
            #pragma unroll
            for (int nt = 0; nt < 8; nt++)
                #pragma unroll
                for (int c = 0; c < 4; c++) acc[mt][nt][c] = 0.f;

        #pragma unroll
        for (int ks = 0; ks < 8; ks++) {
            uint32_t a[4][4];
            #pragma unroll
            for (int mt = 0; mt < 4; mt++)
                ldsm4(a[mt][0], a[mt][1], a[mt][2], a[mt][3],
                      aBase + mt * (16 * LDB) + ks * 32);
            uint32_t b0[8], b1[8];
            #pragma unroll
            for (int np = 0; np < 4; np++) {
                uint32_t r0, r1, r2, r3;
                ldsm4(r0, r1, r2, r3,
                      bBase + buf * 34816 + np * (16 * LDB) + ks * 32);
                b0[np * 2] = r0; b1[np * 2] = r2;
                b0[np * 2 + 1] = r1; b1[np * 2 + 1] = r3;
            }
            #pragma unroll
            for (int mt = 0; mt < 4; mt++)
                #pragma unroll
                for (int nt = 0; nt < 8; nt++)
                    mma16816(acc[mt][nt], a[mt], b0[nt], b1[nt]);
        }

        // ---- per-thread row minima (8 row-slots) ----
        float lm[8];
        #pragma unroll
        for (int mt = 0; mt < 4; mt++) {
            #pragma unroll
            for (int h = 0; h < 2; h++) {
                float m = 1e30f;
                #pragma unroll
                for (int nt = 0; nt < 8; nt++) {
                    int colb = wn * 64 + nt * 8 + (lane & 3) * 2;
                    float s0 = cns[buf * 128 + colb]     - acc[mt][nt][h * 2];
                    float s1 = cns[buf * 128 + colb + 1] - acc[mt][nt][h * 2 + 1];
                    m = fminf(m, fminf(s0, s1));
                }
                lm[mt * 2 + h] = m;
            }
        }
        #pragma unroll
        for (int s = 0; s < 8; s++) {
            lm[s] = fminf(lm[s], __shfl_xor_sync(0xffffffffu, lm[s], 1));
            lm[s] = fminf(lm[s], __shfl_xor_sync(0xffffffffu, lm[s], 2));
        }
        if ((lane & 3) == 0) {
            #pragma unroll
            for (int mt = 0; mt < 4; mt++)
                #pragma unroll
                for (int h = 0; h < 2; h++) {
                    int row = wm * 64 + mt * 16 + (lane >> 2) + h * 8;
                    rmin[wn * 256 + row] = lm[mt * 2 + h];
                }
        }
        __syncthreads();
        {   // row-global running min + threshold (thread tid owns row tid)
            float tm = fminf(rmin[tid], rmin[256 + tid]);
            float r  = fminf(rm[tid], tm);
            rm[tid]  = r;
            rmin[tid] = r + eb2[tid];     // reuse rmin[0..255] as thr
        }
        __syncthreads();

        // ---- candidate collection ----
        #pragma unroll
        for (int mt = 0; mt < 4; mt++) {
            #pragma unroll
            for (int h = 0; h < 2; h++) {
                int row = wm * 64 + mt * 16 + (lane >> 2) + h * 8;
                float thrv = rmin[row];
                if (lm[mt * 2 + h] < thrv) {
                    int tok = tt * 256 + row;
                    #pragma unroll
                    for (int nt = 0; nt < 8; nt++) {
                        int colb = wn * 64 + nt * 8 + (lane & 3) * 2;
                        #pragma unroll
                        for (int cc = 0; cc < 2; cc++) {
                            float sc = cns[buf * 128 + colb + cc] - acc[mt][nt][h * 2 + cc];
                            if (sc < thrv) {
                                int pos = atomicAdd(&g_ccount[tok], 1);
                                if (pos < CAP)
                                    g_cand[tok * CAP + pos] = kb0 + it * 128 + colb + cc;
                            }
                        }
                    }
                }
            }
        }
        __syncthreads();   // done reading cns[buf]/B[buf]

        if (it + 2 < NIT) {
            vq_loadB(su, buf, kb0 + (it + 2) * 128, tid);
            CP_COMMIT();
            if (tid < 128) cns[buf * 128 + tid] = g_cnorm[kb0 + (it + 2) * 128 + tid];
        }
        if (it + 1 < NIT) {
            if (it + 2 < NIT) { CP_WAIT1(); } else { CP_WAIT0(); }
            __syncthreads();
        }
    }
}

// ============================================================
// Exact fp32 re-rank of candidates (one warp per token)
// ============================================================
__global__ void k_rescore(const float* __restrict__ cb) {
    int gw   = (blockIdx.x * blockDim.x + threadIdx.x) >> 5;
    int lane = threadIdx.x & 31;
    if (gw >= NN) return;
    int cnt = g_ccount[gw];
    const float* xp = g_x + (size_t)gw * DD;
    float x4[4];
    #pragma unroll
    for (int t = 0; t < 4; t++) x4[t] = xp[lane + t * 32];

    float bestv = 1e30f;
    int   bestk = KB;

    if (cnt <= CAP) {
        for (int i = 0; i < cnt; i++) {
            int k = g_cand[gw * CAP + i];
            const float* cp = cb + (size_t)k * DD;
            float p = 0.f;
            #pragma unroll
            for (int t = 0; t < 4; t++) p = fmaf(x4[t], cp[lane + t * 32], p);
            #pragma unroll
            for (int o = 16; o; o >>= 1) p += __shfl_xor_sync(0xffffffffu, p, o);
            float sc = g_cnorm[k] - p;
            if (sc < bestv || (sc == bestv && k < bestk)) { bestv = sc; bestk = k; }
        }
    } else {
        for (int k = lane; k < KB; k += 32) {
            const float* cp = cb + (size_t)k * DD;
            float p = 0.f;
            for (int d = 0; d < DD; d++) p = fmaf(__ldg(xp + d), __ldg(cp + d), p);
            float sc = g_cnorm[k] - p;
            if (sc < bestv || (sc == bestv && k < bestk)) { bestv = sc; bestk = k; }
        }
        #pragma unroll
        for (int o = 16; o; o >>= 1) {
            float ov = __shfl_down_sync(0xffffffffu, bestv, o);
            int   ok = __shfl_down_sync(0xffffffffu, bestk, o);
            if (ov < bestv || (ov == bestv && ok < bestk)) { bestv = ov; bestk = ok; }
        }
        bestk = __shfl_sync(0xffffffffu, bestk, 0);
    }
    if (lane == 0) g_idx[gw] = bestk;
}

// ============================================================
// Post (unchanged)
// ============================================================
__global__ void k_post(const float* __restrict__ cb, const float* __restrict__ rv) {
    int gw   = (blockIdx.x * blockDim.x + threadIdx.x) >> 5;
    int lane = threadIdx.x & 31;
    if (gw >= NN) return;
    int idx = g_idx[gw];
    const float* xp = g_x + (size_t)gw * DD;
    const float* cp = cb + (size_t)idx * DD;
    const float* rp = rv + (size_t)gw * DD;
    float xr[4], rr[4];
    float sr = 0.f, sn = 0.f;
    #pragma unroll
    for (int t = 0; t < 4; t++) {
        int d = lane + t * 32;
        float xv = xp[d], cv = cp[d], rvv = rp[d];
        xr[t] = xv; rr[t] = rvv;
        float df = xv - cv;
        sr += df * df;
        sn += rvv * rvv;
    }
    #pragma unroll
    for (int o = 16; o; o >>= 1) {
        sr += __shfl_xor_sync(0xffffffffu, sr, o);
        sn += __shfl_xor_sync(0xffffffffu, sn, o);
    }
    float ratio = sqrtf(sr) / sqrtf(sn) + 1e-12f;
    float* qp = g_q + (size_t)gw * DD;
    #pragma unroll
    for (int t = 0; t < 4; t++) qp[lane + t * 32] = xr[t] + ratio * rr[t];
    if (lane == 0) atomicAdd(&g_counts[idx], 1.0f);
}

// ============================================================
// Final scalars (unchanged)
// ============================================================
__global__ void k_final(const int* __restrict__ used, float* __restrict__ out) {
    __shared__ float red[256];
    int tid = threadIdx.x;
    float s = 0.f;
    for (int k = tid; k < KB; k += 256) {
        float p = g_counts[k] * (1.0f / 8192.0f);
        s += p * logf(p + 1e-12f);
    }
    red[tid] = s;
    __syncthreads();
    for (int o = 128; o; o >>= 1) {
        if (tid < o) red[tid] += red[tid + o];
        __syncthreads();
    }
    if (tid == 0) out[4194304] = expf(-red[0]);
    for (int k = tid; k < KB; k += 256)
        out[4194305 + k] = (float)(used[k] + (int)g_counts[k]);
    for (int n = tid; n < NN; n += 256)
        out[4194305 + KB + n] = (float)g_idx[n];
}

// ============================================================
// Decode GEMM (unchanged)
// ============================================================
__global__ void __launch_bounds__(256) k_dec(const float* __restrict__ Wout,
                                             const float* __restrict__ bout,
                                             float* __restrict__ out) {
    __shared__ float As[16][132];
    __shared__ float Bs[16][128];
    int tid  = threadIdx.x;
    int m0   = (blockIdx.x >> 2) * 128;
    int n0   = (blockIdx.x & 3) * 128;
    int row0 = (tid >> 4) << 3;
    int col0 = (tid & 15) << 3;

    float acc[8][8];
    #pragma unroll
    for (int i = 0; i < 8; i++)
        #pragma unroll
        for (int j = 0; j < 8; j++) acc[i][j] = 0.f;

    for (int k0 = 0; k0 < DD; k0 += 16) {
        #pragma unroll
        for (int it = 0; it < 2; it++) {
            int v  = it * 256 + tid;
            int kl = v >> 5;
            int r  = v & 31;
            int bl = r >> 4;
            int j4 = (r & 15) << 2;
            int bg = (m0 >> 6) + bl;
            float4 val = *(const float4*)&g_q[(size_t)bg * 8192 + (k0 + kl) * 64 + j4];
            *(float4*)&As[kl][bl * 64 + j4] = val;
        }
        {
            int n4 = (tid & 31) << 2;
            int kr = tid >> 5;
            #pragma unroll
            for (int pass = 0; pass < 2; pass++)
                *(float4*)&Bs[kr + pass * 8][n4] =
                    *(const float4*)(Wout + (size_t)(k0 + kr + pass * 8) * DIMI + n0 + n4);
        }
        __syncthreads();
        #pragma unroll
        for (int kk = 0; kk < 16; kk++) {
            float a[8], b[8];
            *(float4*)(a)     = *(const float4*)&As[kk][row0];
            *(float4*)(a + 4) = *(const float4*)&As[kk][row0 + 4];
            *(float4*)(b)     = *(const float4*)&Bs[kk][col0];
            *(float4*)(b + 4) = *(const float4*)&Bs[kk][col0 + 4];
            #pragma unroll
            for (int i = 0; i < 8; i++)
                #pragma unroll
                for (int j = 0; j < 8; j++) acc[i][j] += a[i] * b[j];
        }
        __syncthreads();
    }
    #pragma unroll
    for (int i = 0; i < 8; i++) {
        #pragma unroll
        for (int j = 0; j < 8; j++) {
            out[(size_t)(m0 + row0 + i) * DIMI + n0 + col0 + j] =
                acc[i][j] + bout[n0 + col0 + j];
        }
    }
}

// ============================================================
extern "C" void kernel_launch(void* const* d_in, const int* in_sizes, int n_in,
                              void* d_out, int out_size) {
    (void)in_sizes; (void)n_in; (void)out_size;
    const float* in_f   = (const float*)d_in[0];
    const float* in_l   = (const float*)d_in[1];
    const float* rv     = (const float*)d_in[2];
    const float* cb     = (const float*)d_in[3];
    const float* W_in   = (const float*)d_in[4];
    const float* conv_w = (const float*)d_in[6];
    const float* W_out  = (const float*)d_in[8];
    const float* b_out  = (const float*)d_in[9];
    const int*   used   = (const int*)d_in[10];
    float* out = (float*)d_out;

    cudaFuncSetAttribute(k_vqtc, cudaFuncAttributeMaxDynamicSharedMemorySize, VQ_SMEM);

    k_prep   <<<576, 256>>>(conv_w);
    k_cnorm  <<<64, 256>>>(cb);
    k_splitc <<<8192, 256>>>(cb);
    k_gemm1  <<<256, 256>>>(in_l, in_f, W_in);
    k_conv   <<<128, 256>>>();
    k_splitx <<<1024, 256>>>();
    k_vqtc   <<<128, 256, VQ_SMEM>>>();
    k_rescore<<<1024, 256>>>(cb);
    k_post   <<<1024, 256>>>(cb, rv);
    k_final  <<<1, 256>>>(used, out);
    k_dec    <<<256, 256>>>(W_out, b_out, out);
}

// round 5
// speedup vs baseline: 2.4007x; 1.1436x over previous
#include <cuda_runtime.h>
#include <cuda_bf16.h>
#include <math.h>
#include <stdint.h>

// ---------------- problem dims ----------------
#define KB   16384
#define NN   8192
#define M1   32768
#define DD   128
#define DIMI 512
#define CAP  64

// ---------------- scratch ----------------
__device__ float g_h[M1 * DD];
__device__ float g_x[NN * DD];
__device__ float g_q[NN * DD];
__device__ float g_cnorm[KB];
__device__ float g_counts[KB];
__device__ int   g_idx[NN];
__device__ __nv_bfloat16 g_xs[NN * DD];           // x hi (bf16)
__device__ __nv_bfloat16 g_cs[(size_t)KB * DD];   // codebook hi (bf16)
__device__ float g_xnorm[NN];
__device__ int   g_cmax_bits;
__device__ int   g_ccount[NN];
__device__ int   g_cand[NN * CAP];
// tf32-split weights
__device__ float g_whi[DIMI * DD];                // W_in hi  [k][n]
__device__ float g_wlo[DIMI * DD];                // W_in lo
__device__ float g_wthi[9 * DD * DD];             // conv w hi [kk][din][dout]
__device__ float g_wtlo[9 * DD * DD];

// ---------------- helpers ----------------
__device__ __forceinline__ uint32_t smem_u32(const void* p) {
    uint32_t a;
    asm("{ .reg .u64 t; cvta.to.shared.u64 t, %1; cvt.u32.u64 %0, t; }" : "=r"(a) : "l"(p));
    return a;
}
__device__ __forceinline__ void cp16(uint32_t dst, const void* src) {
    asm volatile("cp.async.cg.shared.global [%0], [%1], 16;\n" :: "r"(dst), "l"(src));
}
__device__ __forceinline__ void cp16z(uint32_t dst, const void* src, int sz) {
    asm volatile("cp.async.cg.shared.global [%0], [%1], 16, %2;\n" :: "r"(dst), "l"(src), "r"(sz));
}
#define CP_COMMIT()  asm volatile("cp.async.commit_group;\n" ::: "memory")
#define CP_WAIT0()   asm volatile("cp.async.wait_group 0;\n" ::: "memory")
#define CP_WAIT1()   asm volatile("cp.async.wait_group 1;\n" ::: "memory")

__device__ __forceinline__ void ldsm4(uint32_t& r0, uint32_t& r1, uint32_t& r2, uint32_t& r3,
                                      uint32_t a) {
    asm volatile("ldmatrix.sync.aligned.m8n8.x4.shared.b16 {%0,%1,%2,%3}, [%4];"
                 : "=r"(r0), "=r"(r1), "=r"(r2), "=r"(r3) : "r"(a));
}
__device__ __forceinline__ void mma16816(float* d, const uint32_t* a, uint32_t b0, uint32_t b1) {
    asm volatile("mma.sync.aligned.m16n8k16.row.col.f32.bf16.bf16.f32 "
                 "{%0,%1,%2,%3}, {%4,%5,%6,%7}, {%8,%9}, {%0,%1,%2,%3};"
                 : "+f"(d[0]), "+f"(d[1]), "+f"(d[2]), "+f"(d[3])
                 : "r"(a[0]), "r"(a[1]), "r"(a[2]), "r"(a[3]), "r"(b0), "r"(b1));
}
__device__ __forceinline__ void mma_tf32(float* d, const uint32_t* a, uint32_t b0, uint32_t b1) {
    asm volatile("mma.sync.aligned.m16n8k8.row.col.f32.tf32.tf32.f32 "
                 "{%0,%1,%2,%3}, {%4,%5,%6,%7}, {%8,%9}, {%0,%1,%2,%3};"
                 : "+f"(d[0]), "+f"(d[1]), "+f"(d[2]), "+f"(d[3])
                 : "r"(a[0]), "r"(a[1]), "r"(a[2]), "r"(a[3]), "r"(b0), "r"(b1));
}
__device__ __forceinline__ void tf32split(float a, uint32_t& hi, uint32_t& lo) {
    asm("cvt.rna.tf32.f32 %0, %1;" : "=r"(hi) : "f"(a));
    float lof = a - __uint_as_float(hi);
    asm("cvt.rna.tf32.f32 %0, %1;" : "=r"(lo) : "f"(lof));
}

// ============================================================
// Prep: conv weight transpose + tf32 split ; W_in tf32 split
// ============================================================
__global__ void k_prep_c(const float* __restrict__ cw) {
    int i = blockIdx.x * 256 + threadIdx.x;
    if (i == 0) g_cmax_bits = 0;
    if (i < 9 * DD * DD) {
        int dout = i & 127;
        int din  = (i >> 7) & 127;
        int kk   = i >> 14;
        float w = cw[(dout * DD + din) * 9 + kk];
        uint32_t hi, lo;
        tf32split(w, hi, lo);
        g_wthi[kk * (DD * DD) + din * DD + dout] = __uint_as_float(hi);
        g_wtlo[kk * (DD * DD) + din * DD + dout] = __uint_as_float(lo);
    }
}
__global__ void k_prep_w(const float* __restrict__ W) {
    int i = blockIdx.x * 256 + threadIdx.x;
    if (i < DIMI * DD) {
        uint32_t hi, lo;
        tf32split(W[i], hi, lo);
        g_whi[i] = __uint_as_float(hi);
        g_wlo[i] = __uint_as_float(lo);
    }
}

// ============================================================
// cnorm (0.5*|c|^2), cmax, zero counters
// ============================================================
__global__ void k_cnorm(const float* __restrict__ cb) {
    int k = blockIdx.x * 256 + threadIdx.x;
    if (k < KB) {
        const float4* p = (const float4*)(cb + (size_t)k * DD);
        float s = 0.f;
        #pragma unroll
        for (int i = 0; i < 32; i++) {
            float4 v = p[i];
            s += v.x * v.x + v.y * v.y + v.z * v.z + v.w * v.w;
        }
        g_cnorm[k]  = 0.5f * s;
        g_counts[k] = 0.f;
        if (k < NN) g_ccount[k] = 0;
        atomicMax(&g_cmax_bits, __float_as_int(sqrtf(s)));
    }
}

__global__ void k_splitc(const float* __restrict__ cb) {
    int i = blockIdx.x * 256 + threadIdx.x;
    if (i < KB * DD) g_cs[i] = __float2bfloat16(cb[i]);
}

// ============================================================
// x hi split + |x| (one warp per token)
// ============================================================
__global__ void k_splitx() {
    int gw   = blockIdx.x * 8 + (threadIdx.x >> 5);
    int lane = threadIdx.x & 31;
    const float* xp = g_x + (size_t)gw * DD;
    float ss = 0.f;
    #pragma unroll
    for (int t = 0; t < 4; t++) {
        float v = xp[lane + t * 32];
        g_xs[(size_t)gw * DD + lane + t * 32] = __float2bfloat16(v);
        ss += v * v;
    }
    #pragma unroll
    for (int o = 16; o; o >>= 1) ss += __shfl_xor_sync(0xffffffffu, ss, o);
    if (lane == 0) g_xnorm[gw] = sqrtf(ss);
}

// ============================================================
// GEMM1 via 3xTF32: g_h = (A1-A0) @ W_in
// M=32768, K=512, N=128. CTA 128m x 128n, 256 CTAs, 8 warps (4M x 2N).
// smem float layout: A1[2][128][36] | A0[2][128][36] | BH[2][32][136] | BL[2][32][136]
// ============================================================
#define G1_SMEM 143360
__global__ void __launch_bounds__(256, 1) k_gemm1(const float* __restrict__ A1,
                                                  const float* __restrict__ A0) {
    extern __shared__ char smc[];
    float*   fs = (float*)smc;
    uint32_t su = smem_u32(smc);
    int tid  = threadIdx.x;
    int wid  = tid >> 5;
    int lane = tid & 31;
    int g    = lane >> 2;
    int t    = lane & 3;
    int wm   = wid & 3;
    int wn   = wid >> 2;
    int m0   = blockIdx.x * 128;

    float acc[2][8][4];
    #pragma unroll
    for (int i = 0; i < 2; i++)
        #pragma unroll
        for (int j = 0; j < 8; j++)
            #pragma unroll
            for (int c = 0; c < 4; c++) acc[i][j][c] = 0.f;

    // chunk issue: k-chunk of 32
    auto issue = [&](int ch, int buf) {
        int k0 = ch * 32;
        #pragma unroll
        for (int it = 0; it < 4; it++) {
            int idx = it * 256 + tid;
            int row = idx >> 3;
            int c4  = idx & 7;
            cp16(su + buf * 18432 + row * 144 + c4 * 16,
                 A1 + (size_t)(m0 + row) * DIMI + k0 + c4 * 4);
            cp16(su + 36864 + buf * 18432 + row * 144 + c4 * 16,
                 A0 + (size_t)(m0 + row) * DIMI + k0 + c4 * 4);
        }
        #pragma unroll
        for (int it = 0; it < 4; it++) {
            int idx = it * 256 + tid;
            int row = idx >> 5;
            int c   = idx & 31;
            cp16(su + 73728 + buf * 17408 + row * 544 + c * 16,
                 g_whi + (size_t)(k0 + row) * DD + c * 4);
            cp16(su + 108544 + buf * 17408 + row * 544 + c * 16,
                 g_wlo + (size_t)(k0 + row) * DD + c * 4);
        }
        CP_COMMIT();
    };

    issue(0, 0);
    issue(1, 1);

    for (int ch = 0; ch < 16; ch++) {
        int buf = ch & 1;
        if (ch < 15) { CP_WAIT1(); } else { CP_WAIT0(); }
        __syncthreads();

        const float* A1f = fs + buf * 4608;
        const float* A0f = fs + 9216 + buf * 4608;
        const float* BHf = fs + 18432 + buf * 4352;
        const float* BLf = fs + 27136 + buf * 4352;

        #pragma unroll
        for (int kc = 0; kc < 4; kc++) {
            uint32_t ah[2][4], al[2][4];
            #pragma unroll
            for (int mt = 0; mt < 2; mt++) {
                int r0 = wm * 32 + mt * 16 + g;
                int c0 = kc * 8 + t;
                float d0 = A1f[r0 * 36 + c0]           - A0f[r0 * 36 + c0];
                float d1 = A1f[(r0 + 8) * 36 + c0]     - A0f[(r0 + 8) * 36 + c0];
                float d2 = A1f[r0 * 36 + c0 + 4]       - A0f[r0 * 36 + c0 + 4];
                float d3 = A1f[(r0 + 8) * 36 + c0 + 4] - A0f[(r0 + 8) * 36 + c0 + 4];
                tf32split(d0, ah[mt][0], al[mt][0]);
                tf32split(d1, ah[mt][1], al[mt][1]);
                tf32split(d2, ah[mt][2], al[mt][2]);
                tf32split(d3, ah[mt][3], al[mt][3]);
            }
            uint32_t bh[8][2], bl[8][2];
            #pragma unroll
            for (int nt = 0; nt < 8; nt++) {
                int n  = wn * 64 + nt * 8 + g;
                int kr = kc * 8 + t;
                bh[nt][0] = __float_as_uint(BHf[kr * 136 + n]);
                bh[nt][1] = __float_as_uint(BHf[(kr + 4) * 136 + n]);
                bl[nt][0] = __float_as_uint(BLf[kr * 136 + n]);
                bl[nt][1] = __float_as_uint(BLf[(kr + 4) * 136 + n]);
            }
            #pragma unroll
            for (int mt = 0; mt < 2; mt++)
                #pragma unroll
                for (int nt = 0; nt < 8; nt++) {
                    mma_tf32(acc[mt][nt], ah[mt], bh[nt][0], bh[nt][1]);
                    mma_tf32(acc[mt][nt], al[mt], bh[nt][0], bh[nt][1]);
                    mma_tf32(acc[mt][nt], ah[mt], bl[nt][0], bl[nt][1]);
                }
        }
        __syncthreads();
        if (ch + 2 < 16) issue(ch + 2, buf);
    }

    #pragma unroll
    for (int mt = 0; mt < 2; mt++)
        #pragma unroll
        for (int nt = 0; nt < 8; nt++) {
            int r  = m0 + wm * 32 + mt * 16 + g;
            int cc = wn * 64 + nt * 8 + 2 * t;
            *(float2*)&g_h[(size_t)r * DD + cc]       = make_float2(acc[mt][nt][0], acc[mt][nt][1]);
            *(float2*)&g_h[(size_t)(r + 8) * DD + cc] = make_float2(acc[mt][nt][2], acc[mt][nt][3]);
        }
}

// ============================================================
// Conv via 3xTF32: 9 accumulated GEMMs, A gathered from g_h with zero halo.
// CTA: 64 p x 128 dout, 128 CTAs, 8 warps (2M x 4N).
// smem: A[2][64][68] | BH[2][64][136] | BL[2][64][136]
// ============================================================
#define CV_SMEM 174080
__global__ void __launch_bounds__(256, 1) k_conv() {
    extern __shared__ char smc[];
    float*   fs = (float*)smc;
    uint32_t su = smem_u32(smc);
    int tid  = threadIdx.x;
    int wid  = tid >> 5;
    int lane = tid & 31;
    int g    = lane >> 2;
    int t    = lane & 3;
    int wm   = wid & 1;
    int wn   = wid >> 1;
    int p0   = blockIdx.x * 64;

    float acc[2][4][4];
    #pragma unroll
    for (int i = 0; i < 2; i++)
        #pragma unroll
        for (int j = 0; j < 4; j++)
            #pragma unroll
            for (int c = 0; c < 4; c++) acc[i][j][c] = 0.f;

    auto issue = [&](int s, int buf) {
        int kk = s >> 1;
        int ch = s & 1;
        int kh = kk / 3, kw = kk % 3;
        #pragma unroll
        for (int it = 0; it < 4; it++) {
            int idx = it * 256 + tid;
            int pl  = idx >> 4;
            int cf  = idx & 15;
            int p  = p0 + pl;
            int b  = p >> 6;
            int jj = p & 63;
            int oh = jj >> 3, ow = jj & 7;
            int ih = 2 * oh - 1 + kh;
            int iw = 2 * ow - 1 + kw;
            bool valid = ((unsigned)ih < 16u) && ((unsigned)iw < 16u);
            const float* src = valid
                ? g_h + ((size_t)(b * 256 + ih * 16 + iw) * DD + ch * 64 + cf * 4)
                : g_h;
            cp16z(su + buf * 17408 + pl * 272 + cf * 16, src, valid ? 16 : 0);
        }
        #pragma unroll
        for (int it = 0; it < 8; it++) {
            int idx = it * 256 + tid;
            int row = idx >> 5;
            int c   = idx & 31;
            size_t so = (size_t)kk * (DD * DD) + (size_t)(ch * 64 + row) * DD + c * 4;
            cp16(su + 34816 + buf * 34816 + row * 544 + c * 16, g_wthi + so);
            cp16(su + 104448 + buf * 34816 + row * 544 + c * 16, g_wtlo + so);
        }
        CP_COMMIT();
    };

    issue(0, 0);
    issue(1, 1);

    for (int s = 0; s < 18; s++) {
        int buf = s & 1;
        if (s < 17) { CP_WAIT1(); } else { CP_WAIT0(); }
        __syncthreads();

        const float* Af  = fs + buf * 4352;
        const float* BHf = fs + 8704 + buf * 8704;
        const float* BLf = fs + 26112 + buf * 8704;

        #pragma unroll
        for (int kc = 0; kc < 8; kc++) {
            uint32_t ah[2][4], al[2][4];
            #pragma unroll
            for (int mt = 0; mt < 2; mt++) {
                int r0 = wm * 32 + mt * 16 + g;
                int c0 = kc * 8 + t;
                tf32split(Af[r0 * 68 + c0],           ah[mt][0], al[mt][0]);
                tf32split(Af[(r0 + 8) * 68 + c0],     ah[mt][1], al[mt][1]);
                tf32split(Af[r0 * 68 + c0 + 4],       ah[mt][2], al[mt][2]);
                tf32split(Af[(r0 + 8) * 68 + c0 + 4], ah[mt][3], al[mt][3]);
            }
            uint32_t bh[4][2], bl[4][2];
            #pragma unroll
            for (int nt = 0; nt < 4; nt++) {
                int n  = wn * 32 + nt * 8 + g;
                int kr = kc * 8 + t;
                bh[nt][0] = __float_as_uint(BHf[kr * 136 + n]);
                bh[nt][1] = __float_as_uint(BHf[(kr + 4) * 136 + n]);
                bl[nt][0] = __float_as_uint(BLf[kr * 136 + n]);
                bl[nt][1] = __float_as_uint(BLf[(kr + 4) * 136 + n]);
            }
            #pragma unroll
            for (int mt = 0; mt < 2; mt++)
                #pragma unroll
                for (int nt = 0; nt < 4; nt++) {
                    mma_tf32(acc[mt][nt], ah[mt], bh[nt][0], bh[nt][1]);
                    mma_tf32(acc[mt][nt], al[mt], bh[nt][0], bh[nt][1]);
                    mma_tf32(acc[mt][nt], ah[mt], bl[nt][0], bl[nt][1]);
                }
        }
        __syncthreads();
        if (s + 2 < 18) issue(s + 2, buf);
    }

    #pragma unroll
    for (int mt = 0; mt < 2; mt++)
        #pragma unroll
        for (int nt = 0; nt < 4; nt++) {
            int r  = p0 + wm * 32 + mt * 16 + g;
            int cc = wn * 32 + nt * 8 + 2 * t;
            *(float2*)&g_x[(size_t)r * DD + cc]       = make_float2(acc[mt][nt][0], acc[mt][nt][1]);
            *(float2*)&g_x[(size_t)(r + 8) * DD + cc] = make_float2(acc[mt][nt][2], acc[mt][nt][3]);
        }
}

// ============================================================
// VQ approximate pass via mma.sync bf16 (hi only) + margin collect.
// (unchanged from passing round 4)
// ============================================================
#define LDB      272
#define A_OFF    0
#define B_OFF    69632
#define CNS_OFF  139264
#define EB2_OFF  140288
#define RMIN_OFF 141312
#define RM_OFF   143360
#define VQ_SMEM  144384
#define NIT 32

__device__ __forceinline__ void vq_loadB(uint32_t su, int buf, int kglob, int tid) {
    #pragma unroll
    for (int t = 0; t < 8; t++) {
        int j   = t * 256 + tid;
        int row = j >> 4;
        int c   = j & 15;
        cp16(su + B_OFF + buf * 34816 + row * LDB + c * 16,
             (const char*)g_cs + ((size_t)(kglob + row) * DD + c * 8) * 2);
    }
}

__global__ void __launch_bounds__(256, 1) k_vqtc() {
    extern __shared__ char smc[];
    uint32_t su = smem_u32(smc);
    int tid  = threadIdx.x;
    int wid  = tid >> 5;
    int lane = tid & 31;
    int wm   = wid & 3;
    int wn   = wid >> 2;
    int tt   = blockIdx.x >> 2;
    int sp   = blockIdx.x & 3;
    int kb0  = sp * 4096;

    float* cns  = (float*)(smc + CNS_OFF);
    float* eb2  = (float*)(smc + EB2_OFF);
    float* rmin = (float*)(smc + RMIN_OFF);
    float* rm   = (float*)(smc + RM_OFF);

    #pragma unroll
    for (int t = 0; t < 16; t++) {
        int i   = t * 256 + tid;
        int row = i >> 4;
        int c   = i & 15;
        cp16(su + A_OFF + row * LDB + c * 16,
             (const char*)g_xs + ((size_t)(tt * 256 + row) * DD + c * 8) * 2);
    }
    vq_loadB(su, 0, kb0, tid);
    CP_COMMIT();
    vq_loadB(su, 1, kb0 + 128, tid);
    CP_COMMIT();

    if (tid < 128) {
        cns[tid]       = g_cnorm[kb0 + tid];
        cns[128 + tid] = g_cnorm[kb0 + 128 + tid];
    }
    {
        float cmax = __int_as_float(g_cmax_bits);
        float xn = g_xnorm[tt * 256 + tid];
        eb2[tid] = 2.f * (0.0041f * xn * cmax) + 0.1f;
        rm[tid] = 1e30f;
    }
    CP_WAIT1();
    __syncthreads();

    uint32_t aBase = su + A_OFF + (wm * 64 + (lane & 15)) * LDB + (lane >> 4) * 16;
    uint32_t bBase = su + B_OFF + (wn * 64 + (lane & 15)) * LDB + (lane >> 4) * 16;

    for (int it = 0; it < NIT; it++) {
        int buf = it & 1;
        float acc[4][8][4];
        #pragma unroll
        for (int mt = 0; mt < 4; mt++)
            #pragma unroll
            for (int nt = 0; nt < 8; nt++)
                #pragma unroll
                for (int c = 0; c < 4; c++) acc[mt][nt][c] = 0.f;

        #pragma unroll
        for (int ks = 0; ks < 8; ks++) {
            uint32_t a[4][4];
            #pragma unroll
            for (int mt = 0; mt < 4; mt++)
                ldsm4(a[mt][0], a[mt][1], a[mt][2], a[mt][3],
                      aBase + mt * (16 * LDB) + ks * 32);
            uint32_t b0[8], b1[8];
            #pragma unroll
            for (int np = 0; np < 4; np++) {
                uint32_t r0, r1, r2, r3;
                ldsm4(r0, r1, r2, r3,
                      bBase + buf * 34816 + np * (16 * LDB) + ks * 32);
                b0[np * 2] = r0; b1[np * 2] = r2;
                b0[np * 2 + 1] = r1; b1[np * 2 + 1] = r3;
            }
            #pragma unroll
            for (int mt = 0; mt < 4; mt++)
                #pragma unroll
                for (int nt = 0; nt < 8; nt++)
                    mma16816(acc[mt][nt], a[mt], b0[nt], b1[nt]);
        }

        float lm[8];
        #pragma unroll
        for (int mt = 0; mt < 4; mt++) {
            #pragma unroll
            for (int h = 0; h < 2; h++) {
                float m = 1e30f;
                #pragma unroll
                for (int nt = 0; nt < 8; nt++) {
                    int colb = wn * 64 + nt * 8 + (lane & 3) * 2;
                    float s0 = cns[buf * 128 + colb]     - acc[mt][nt][h * 2];
                    float s1 = cns[buf * 128 + colb + 1] - acc[mt][nt][h * 2 + 1];
                    m = fminf(m, fminf(s0, s1));
                }
                lm[mt * 2 + h] = m;
            }
        }
        #pragma unroll
        for (int s = 0; s < 8; s++) {
            lm[s] = fminf(lm[s], __shfl_xor_sync(0xffffffffu, lm[s], 1));
            lm[s] = fminf(lm[s], __shfl_xor_sync(0xffffffffu, lm[s], 2));
        }
        if ((lane & 3) == 0) {
            #pragma unroll
            for (int mt = 0; mt < 4; mt++)
                #pragma unroll
                for (int h = 0; h < 2; h++) {
                    int row = wm * 64 + mt * 16 + (lane >> 2) + h * 8;
                    rmin[wn * 256 + row] = lm[mt * 2 + h];
                }
        }
        __syncthreads();
        {
            float tm = fminf(rmin[tid], rmin[256 + tid]);
            float r  = fminf(rm[tid], tm);
            rm[tid]  = r;
            rmin[tid] = r + eb2[tid];
        }
        __syncthreads();

        #pragma unroll
        for (int mt = 0; mt < 4; mt++) {
            #pragma unroll
            for (int h = 0; h < 2; h++) {
                int row = wm * 64 + mt * 16 + (lane >> 2) + h * 8;
                float thrv = rmin[row];
                if (lm[mt * 2 + h] < thrv) {
                    int tok = tt * 256 + row;
                    #pragma unroll
                    for (int nt = 0; nt < 8; nt++) {
                        int colb = wn * 64 + nt * 8 + (lane & 3) * 2;
                        #pragma unroll
                        for (int cc = 0; cc < 2; cc++) {
                            float sc = cns[buf * 128 + colb + cc] - acc[mt][nt][h * 2 + cc];
                            if (sc < thrv) {
                                int pos = atomicAdd(&g_ccount[tok], 1);
                                if (pos < CAP)
                                    g_cand[tok * CAP + pos] = kb0 + it * 128 + colb + cc;
                            }
                        }
                    }
                }
            }
        }
        __syncthreads();

        if (it + 2 < NIT) {
            vq_loadB(su, buf, kb0 + (it + 2) * 128, tid);
            CP_COMMIT();
            if (tid < 128) cns[buf * 128 + tid] = g_cnorm[kb0 + (it + 2) * 128 + tid];
        }
        if (it + 1 < NIT) {
            if (it + 2 < NIT) { CP_WAIT1(); } else { CP_WAIT0(); }
            __syncthreads();
        }
    }
}

// ============================================================
// Exact fp32 re-rank (unchanged)
// ============================================================
__global__ void k_rescore(const float* __restrict__ cb) {
    int gw   = (blockIdx.x * blockDim.x + threadIdx.x) >> 5;
    int lane = threadIdx.x & 31;
    if (gw >= NN) return;
    int cnt = g_ccount[gw];
    const float* xp = g_x + (size_t)gw * DD;
    float x4[4];
    #pragma unroll
    for (int t = 0; t < 4; t++) x4[t] = xp[lane + t * 32];

    float bestv = 1e30f;
    int   bestk = KB;

    if (cnt <= CAP) {
        for (int i = 0; i < cnt; i++) {
            int k = g_cand[gw * CAP + i];
            const float* cp = cb + (size_t)k * DD;
            float p = 0.f;
            #pragma unroll
            for (int t = 0; t < 4; t++) p = fmaf(x4[t], cp[lane + t * 32], p);
            #pragma unroll
            for (int o = 16; o; o >>= 1) p += __shfl_xor_sync(0xffffffffu, p, o);
            float sc = g_cnorm[k] - p;
            if (sc < bestv || (sc == bestv && k < bestk)) { bestv = sc; bestk = k; }
        }
    } else {
        for (int k = lane; k < KB; k += 32) {
            const float* cp = cb + (size_t)k * DD;
            float p = 0.f;
            for (int d = 0; d < DD; d++) p = fmaf(__ldg(xp + d), __ldg(cp + d), p);
            float sc = g_cnorm[k] - p;
            if (sc < bestv || (sc == bestv && k < bestk)) { bestv = sc; bestk = k; }
        }
        #pragma unroll
        for (int o = 16; o; o >>= 1) {
            float ov = __shfl_down_sync(0xffffffffu, bestv, o);
            int   ok = __shfl_down_sync(0xffffffffu, bestk, o);
            if (ov < bestv || (ov == bestv && ok < bestk)) { bestv = ov; bestk = ok; }
        }
        bestk = __shfl_sync(0xffffffffu, bestk, 0);
    }
    if (lane == 0) g_idx[gw] = bestk;
}

// ============================================================
// Post (unchanged)
// ============================================================
__global__ void k_post(const float* __restrict__ cb, const float* __restrict__ rv) {
    int gw   = (blockIdx.x * blockDim.x + threadIdx.x) >> 5;
    int lane = threadIdx.x & 31;
    if (gw >= NN) return;
    int idx = g_idx[gw];
    const float* xp = g_x + (size_t)gw * DD;
    const float* cp = cb + (size_t)idx * DD;
    const float* rp = rv + (size_t)gw * DD;
    float xr[4], rr[4];
    float sr = 0.f, sn = 0.f;
    #pragma unroll
    for (int t = 0; t < 4; t++) {
        int d = lane + t * 32;
        float xv = xp[d], cv = cp[d], rvv = rp[d];
        xr[t] = xv; rr[t] = rvv;
        float df = xv - cv;
        sr += df * df;
        sn += rvv * rvv;
    }
    #pragma unroll
    for (int o = 16; o; o >>= 1) {
        sr += __shfl_xor_sync(0xffffffffu, sr, o);
        sn += __shfl_xor_sync(0xffffffffu, sn, o);
    }
    float ratio = sqrtf(sr) / sqrtf(sn) + 1e-12f;
    float* qp = g_q + (size_t)gw * DD;
    #pragma unroll
    for (int t = 0; t < 4; t++) qp[lane + t * 32] = xr[t] + ratio * rr[t];
    if (lane == 0) atomicAdd(&g_counts[idx], 1.0f);
}

// ============================================================
// Final scalars (unchanged)
// ============================================================
__global__ void k_final(const int* __restrict__ used, float* __restrict__ out) {
    __shared__ float red[256];
    int tid = threadIdx.x;
    float s = 0.f;
    for (int k = tid; k < KB; k += 256) {
        float p = g_counts[k] * (1.0f / 8192.0f);
        s += p * logf(p + 1e-12f);
    }
    red[tid] = s;
    __syncthreads();
    for (int o = 128; o; o >>= 1) {
        if (tid < o) red[tid] += red[tid + o];
        __syncthreads();
    }
    if (tid == 0) out[4194304] = expf(-red[0]);
    for (int k = tid; k < KB; k += 256)
        out[4194305 + k] = (float)(used[k] + (int)g_counts[k]);
    for (int n = tid; n < NN; n += 256)
        out[4194305 + KB + n] = (float)g_idx[n];
}

// ============================================================
// Decode GEMM (unchanged)
// ============================================================
__global__ void __launch_bounds__(256) k_dec(const float* __restrict__ Wout,
                                             const float* __restrict__ bout,
                                             float* __restrict__ out) {
    __shared__ float As[16][132];
    __shared__ float Bs[16][128];
    int tid  = threadIdx.x;
    int m0   = (blockIdx.x >> 2) * 128;
    int n0   = (blockIdx.x & 3) * 128;
    int row0 = (tid >> 4) << 3;
    int col0 = (tid & 15) << 3;

    float acc[8][8];
    #pragma unroll
    for (int i = 0; i < 8; i++)
        #pragma unroll
        for (int j = 0; j < 8; j++) acc[i][j] = 0.f;

    for (int k0 = 0; k0 < DD; k0 += 16) {
        #pragma unroll
        for (int it = 0; it < 2; it++) {
            int v  = it * 256 + tid;
            int kl = v >> 5;
            int r  = v & 31;
            int bl = r >> 4;
            int j4 = (r & 15) << 2;
            int bg = (m0 >> 6) + bl;
            float4 val = *(const float4*)&g_q[(size_t)bg * 8192 + (k0 + kl) * 64 + j4];
            *(float4*)&As[kl][bl * 64 + j4] = val;
        }
        {
            int n4 = (tid & 31) << 2;
            int kr = tid >> 5;
            #pragma unroll
            for (int pass = 0; pass < 2; pass++)
                *(float4*)&Bs[kr + pass * 8][n4] =
                    *(const float4*)(Wout + (size_t)(k0 + kr + pass * 8) * DIMI + n0 + n4);
        }
        __syncthreads();
        #pragma unroll
        for (int kk = 0; kk < 16; kk++) {
            float a[8], b[8];
            *(float4*)(a)     = *(const float4*)&As[kk][row0];
            *(float4*)(a + 4) = *(const float4*)&As[kk][row0 + 4];
            *(float4*)(b)     = *(const float4*)&Bs[kk][col0];
            *(float4*)(b + 4) = *(const float4*)&Bs[kk][col0 + 4];
            #pragma unroll
            for (int i = 0; i < 8; i++)
                #pragma unroll
                for (int j = 0; j < 8; j++) acc[i][j] += a[i] * b[j];
        }
        __syncthreads();
    }
    #pragma unroll
    for (int i = 0; i < 8; i++) {
        #pragma unroll
        for (int j = 0; j < 8; j++) {
            out[(size_t)(m0 + row0 + i) * DIMI + n0 + col0 + j] =
                acc[i][j] + bout[n0 + col0 + j];
        }
    }
}

// ============================================================
extern "C" void kernel_launch(void* const* d_in, const int* in_sizes, int n_in,
                              void* d_out, int out_size) {
    (void)in_sizes; (void)n_in; (void)out_size;
    const float* in_f   = (const float*)d_in[0];
    const float* in_l   = (const float*)d_in[1];
    const float* rv     = (const float*)d_in[2];
    const float* cb     = (const float*)d_in[3];
    const float* W_in   = (const float*)d_in[4];
    const float* conv_w = (const float*)d_in[6];
    const float* W_out  = (const float*)d_in[8];
    const float* b_out  = (const float*)d_in[9];
    const int*   used   = (const int*)d_in[10];
    float* out = (float*)d_out;

    cudaFuncSetAttribute(k_vqtc,  cudaFuncAttributeMaxDynamicSharedMemorySize, VQ_SMEM);
    cudaFuncSetAttribute(k_gemm1, cudaFuncAttributeMaxDynamicSharedMemorySize, G1_SMEM);
    cudaFuncSetAttribute(k_conv,  cudaFuncAttributeMaxDynamicSharedMemorySize, CV_SMEM);

    k_prep_c <<<576, 256>>>(conv_w);
    k_prep_w <<<256, 256>>>(W_in);
    k_cnorm  <<<64, 256>>>(cb);
    k_splitc <<<8192, 256>>>(cb);
    k_gemm1  <<<256, 256, G1_SMEM>>>(in_l, in_f);
    k_conv   <<<128, 256, CV_SMEM>>>();
    k_splitx <<<1024, 256>>>();
    k_vqtc   <<<128, 256, VQ_SMEM>>>();
    k_rescore<<<1024, 256>>>(cb);
    k_post   <<<1024, 256>>>(cb, rv);
    k_final  <<<1, 256>>>(used, out);
    k_dec    <<<256, 256>>>(W_out, b_out, out);
}